// round 1
// baseline (speedup 1.0000x reference)
#include <cuda_runtime.h>
#include <math.h>

#define NN 50000
#define EE 800000
#define DDIM 128
#define TT 4
#define HH 8
#define DKV 16
#define HDV 8

// ---------------- scratch (static device memory; no allocation) ----------------
__device__ float g_q[NN * DDIM];
__device__ float g_k[NN * DDIM];
__device__ float g_hsub[NN * HH * HDV];
__device__ float g_hneigh[NN * HH * HDV];
__device__ float g_watt[EE * HH];       // exp(att)
__device__ float g_denom[NN * HH];
__device__ int   g_deg[NN];
__device__ int   g_cnt[NN];
__device__ int   g_off[NN + 1];
__device__ int   g_csr[EE];
__device__ int   g_bucket[TT * NN];
__device__ int   g_tcount[TT];

// ---------------- helpers ----------------
__device__ __forceinline__ float ftanh(float x) {
    // tanh(x) = (e^{2x}-1)/(e^{2x}+1); args bounded here, clamp for safety
    float cx = fminf(fmaxf(x, -15.f), 15.f);
    float e  = __expf(2.f * cx);
    return __fdividef(e - 1.f, e + 1.f);
}

__device__ __forceinline__ float gelu_exact(float x) {
    return 0.5f * x * (1.f + erff(x * 0.7071067811865475f));
}

// ---------------- kernels ----------------
__global__ void k_init() {
    int i = blockIdx.x * blockDim.x + threadIdx.x;
    if (i < NN * HH) g_denom[i] = 0.f;
    if (i < NN) { g_deg[i] = 0; g_cnt[i] = 0; }
    if (i < TT) g_tcount[i] = 0;
}

__global__ void k_bucket_deg(const int* __restrict__ ei, const int* __restrict__ ntype) {
    int i = blockIdx.x * blockDim.x + threadIdx.x;
    if (i < EE) atomicAdd(&g_deg[ei[EE + i]], 1);
    if (i < NN) {
        int t = ntype[i];
        int p = atomicAdd(&g_tcount[t], 1);
        g_bucket[t * NN + p] = i;
    }
}

__global__ void k_scan() {
    __shared__ int sums[1024];
    int t = threadIdx.x;
    const int CH = (NN + 1023) / 1024;           // 49
    int b = t * CH;
    int e = min(b + CH, NN);
    int s = 0;
    for (int i = b; i < e; i++) s += g_deg[i];
    sums[t] = s;
    __syncthreads();
    for (int off = 1; off < 1024; off <<= 1) {
        int v = (t >= off) ? sums[t - off] : 0;
        __syncthreads();
        sums[t] += v;
        __syncthreads();
    }
    int run = sums[t] - s;                        // exclusive prefix
    for (int i = b; i < e; i++) { g_off[i] = run; run += g_deg[i]; }
    if (t == 1023) g_off[NN] = sums[1023];
}

__global__ void k_csr(const int* __restrict__ ei) {
    int i = blockIdx.x * blockDim.x + threadIdx.x;
    if (i < EE) {
        int dst = ei[EE + i];
        int pos = g_off[dst] + atomicAdd(&g_cnt[dst], 1);
        g_csr[pos] = i;
    }
}

__global__ void k_hproj(const float* __restrict__ h_mat,
                        const float* __restrict__ hsW, const float* __restrict__ hsb,
                        const float* __restrict__ hnW, const float* __restrict__ hnb) {
    int idx = blockIdx.x * blockDim.x + threadIdx.x;
    if (idx >= NN * 64) return;
    int n = idx >> 6, j = idx & 63;
    float s1 = hsb[j], s2 = hnb[j];
    const float* hm = h_mat + n * 8;
#pragma unroll
    for (int d = 0; d < 8; d++) {
        float v = hm[d];
        s1 += v * hsW[d * 64 + j];
        s2 += v * hnW[d * 64 + j];
    }
    g_hsub[idx] = s1;
    g_hneigh[idx] = s2;
}

// one block = 16 nodes of ONE type; 128 threads = output dims
__global__ void k_proj(const float* __restrict__ xs,
                       const float* __restrict__ subW, const float* __restrict__ subb,
                       const float* __restrict__ neighW, const float* __restrict__ neighb) {
    const int t = blockIdx.y;
    const int cnt = g_tcount[t];
    const int base = blockIdx.x * 16;
    if (base >= cnt) return;
    const int m = min(16, cnt - base);

    __shared__ float sx[16][DDIM];
    __shared__ int nd[16];
    int tid = threadIdx.x;
    if (tid < 16) nd[tid] = (tid < m) ? g_bucket[t * NN + base + tid] : 0;
    __syncthreads();
#pragma unroll
    for (int i = 0; i < 16; i++)
        sx[i][tid] = (i < m) ? xs[nd[i] * DDIM + tid] : 0.f;
    __syncthreads();

    float aq[16], ak[16];
#pragma unroll
    for (int i = 0; i < 16; i++) { aq[i] = 0.f; ak[i] = 0.f; }

    const float* wq = subW + t * DDIM * DDIM + tid;
    const float* wk = neighW + t * DDIM * DDIM + tid;
    for (int d = 0; d < DDIM; d++) {
        float q = __ldg(wq + d * DDIM);
        float k = __ldg(wk + d * DDIM);
#pragma unroll
        for (int i = 0; i < 16; i++) {
            float xv = sx[i][d];
            aq[i] += xv * q;
            ak[i] += xv * k;
        }
    }
    float bq = subb[t * DDIM + tid], bk = neighb[t * DDIM + tid];
    for (int i = 0; i < m; i++) {
        g_q[nd[i] * DDIM + tid] = aq[i] + bq;
        g_k[nd[i] * DDIM + tid] = ak[i] + bk;
    }
}

// one thread = (edge, head)
__global__ void k_att(const int* __restrict__ ei, const int* __restrict__ ntype,
                      const float* __restrict__ ratt, const float* __restrict__ rhatt) {
    int gi = blockIdx.x * blockDim.x + threadIdx.x;
    if (gi >= EE * HH) return;
    int e = gi >> 3;
    int h = gi & 7;
    int src = ei[e], dst = ei[EE + e];
    int st = ntype[dst];

    const float4* q4 = (const float4*)(g_q + dst * DDIM + h * DKV);
    const float4* k4 = (const float4*)(g_k + src * DDIM + h * DKV);
    const float4* r4 = (const float4*)(ratt + (st * HH + h) * DKV);
    float s1 = 0.f;
#pragma unroll
    for (int j = 0; j < 4; j++) {
        float4 qv = q4[j], kv = k4[j], rv = r4[j];
        s1 += ftanh(qv.x * kv.x) * rv.x;
        s1 += ftanh(qv.y * kv.y) * rv.y;
        s1 += ftanh(qv.z * kv.z) * rv.z;
        s1 += ftanh(qv.w * kv.w) * rv.w;
    }

    const float4* hs4 = (const float4*)(g_hsub + dst * 64 + h * 8);
    const float4* hn4 = (const float4*)(g_hneigh + src * 64 + h * 8);
    const float4* rh4 = (const float4*)(rhatt + (st * HH + h) * HDV);
    float s2 = 0.f;
#pragma unroll
    for (int j = 0; j < 2; j++) {
        float4 a = hs4[j], b = hn4[j], r = rh4[j];
        s2 += ftanh(a.x * b.x) * r.x;
        s2 += ftanh(a.y * b.y) * r.y;
        s2 += ftanh(a.z * b.z) * r.z;
        s2 += ftanh(a.w * b.w) * r.w;
    }

    float att = (s1 * 0.25f) * (s2 * 0.3535533905932738f);
    float w = __expf(att);
    g_watt[e * HH + h] = w;
    atomicAdd(&g_denom[dst * HH + h], w);
}

// one warp = one node; lane owns 4 contiguous output dims
__global__ void k_agg(const int* __restrict__ ei,
                      const float* __restrict__ gamma, const float* __restrict__ beta,
                      float* __restrict__ out) {
    int warp = (blockIdx.x * blockDim.x + threadIdx.x) >> 5;
    int lane = threadIdx.x & 31;
    if (warp >= NN) return;
    int n = warp;
    int h = lane >> 2;                       // head for these 4 dims
    float inv = 1.0f / (g_denom[n * HH + h] + 1e-16f);

    int b = g_off[n], e_end = g_off[n + 1];
    float a0 = 0.f, a1 = 0.f, a2 = 0.f, a3 = 0.f;
    for (int p = b; p < e_end; p++) {
        int e = g_csr[p];
        int src = ei[e];
        float al = g_watt[e * HH + h] * inv;
        float4 kv = *(const float4*)(g_k + src * DDIM + lane * 4);
        a0 += al * kv.x; a1 += al * kv.y; a2 += al * kv.z; a3 += al * kv.w;
    }

    float g0 = gelu_exact(a0), g1 = gelu_exact(a1), g2 = gelu_exact(a2), g3 = gelu_exact(a3);

    float s = g0 + g1 + g2 + g3;
#pragma unroll
    for (int o = 16; o; o >>= 1) s += __shfl_xor_sync(0xffffffffu, s, o);
    float mean = s * (1.0f / 128.0f);

    float d0 = g0 - mean, d1 = g1 - mean, d2 = g2 - mean, d3 = g3 - mean;
    float v = d0 * d0 + d1 * d1 + d2 * d2 + d3 * d3;
#pragma unroll
    for (int o = 16; o; o >>= 1) v += __shfl_xor_sync(0xffffffffu, v, o);
    float rs = rsqrtf(v * (1.0f / 128.0f) + 1e-5f);

    int d = lane * 4;
    float4 gm = *(const float4*)(gamma + d);
    float4 bt = *(const float4*)(beta + d);
    float4 ov;
    ov.x = d0 * rs * gm.x + bt.x;
    ov.y = d1 * rs * gm.y + bt.y;
    ov.z = d2 * rs * gm.z + bt.z;
    ov.w = d3 * rs * gm.w + bt.w;
    *(float4*)(out + n * DDIM + d) = ov;
}

// ---------------- launch ----------------
extern "C" void kernel_launch(void* const* d_in, const int* in_sizes, int n_in,
                              void* d_out, int out_size) {
    const float* meta_xs   = (const float*)d_in[0];
    const int*   node_type = (const int*)d_in[1];
    const int*   edge_idx  = (const int*)d_in[2];
    const float* h_mat     = (const float*)d_in[3];
    const float* sub_W     = (const float*)d_in[4];
    const float* sub_b     = (const float*)d_in[5];
    const float* neigh_W   = (const float*)d_in[6];
    const float* neigh_b   = (const float*)d_in[7];
    const float* hsub_W    = (const float*)d_in[8];
    const float* hsub_b    = (const float*)d_in[9];
    const float* hneigh_W  = (const float*)d_in[10];
    const float* hneigh_b  = (const float*)d_in[11];
    const float* rel_att   = (const float*)d_in[12];
    const float* rel_h_att = (const float*)d_in[13];
    const float* ln_gamma  = (const float*)d_in[14];
    const float* ln_beta   = (const float*)d_in[15];
    float* out = (float*)d_out;

    k_init<<<(NN * HH + 255) / 256, 256>>>();
    k_bucket_deg<<<(EE + 255) / 256, 256>>>(edge_idx, node_type);
    k_scan<<<1, 1024>>>();
    k_csr<<<(EE + 255) / 256, 256>>>(edge_idx);
    k_hproj<<<(NN * 64 + 255) / 256, 256>>>(h_mat, hsub_W, hsub_b, hneigh_W, hneigh_b);
    {
        dim3 grid((NN + 15) / 16, TT);
        k_proj<<<grid, 128>>>(meta_xs, sub_W, sub_b, neigh_W, neigh_b);
    }
    k_att<<<(EE * HH + 255) / 256, 256>>>(edge_idx, node_type, rel_att, rel_h_att);
    k_agg<<<(NN * 32 + 255) / 256, 256>>>(edge_idx, ln_gamma, ln_beta, out);
}

// round 2
// speedup vs baseline: 1.5126x; 1.5126x over previous
#include <cuda_runtime.h>
#include <math.h>

#define NN 50000
#define EE 800000
#define DDIM 128
#define TT 4
#define HH 8
#define DKV 16
#define HDV 8

// ---------------- scratch (static device memory; no allocation) ----------------
__device__ float g_q[NN * DDIM];
__device__ float g_k[NN * DDIM];
__device__ float g_hsub[NN * HH * HDV];
__device__ float g_hneigh[NN * HH * HDV];
__device__ int   g_deg[NN];
__device__ int   g_cnt[NN];
__device__ int   g_off[NN + 1];
__device__ int   g_csr[EE];          // stores SRC node id per CSR slot
__device__ int   g_bucket[TT * NN];
__device__ int   g_tcount[TT];

// ---------------- helpers ----------------
__device__ __forceinline__ float ftanh(float x) {
    float y;
    asm("tanh.approx.f32 %0, %1;" : "=f"(y) : "f"(x));
    return y;
}

__device__ __forceinline__ float gelu_exact(float x) {
    return 0.5f * x * (1.f + erff(x * 0.7071067811865475f));
}

// ---------------- kernels ----------------
__global__ void k_zero() {
    int i = blockIdx.x * blockDim.x + threadIdx.x;
    if (i < NN) { g_deg[i] = 0; g_cnt[i] = 0; }
    if (i < TT) g_tcount[i] = 0;
}

__global__ void k_bucket_deg(const int* __restrict__ ei, const int* __restrict__ ntype) {
    int i = blockIdx.x * blockDim.x + threadIdx.x;
    if (i < EE) atomicAdd(&g_deg[ei[EE + i]], 1);
    if (i < NN) {
        int t = ntype[i];
        int p = atomicAdd(&g_tcount[t], 1);
        g_bucket[t * NN + p] = i;
    }
}

__global__ void k_scan() {
    __shared__ int sums[1024];
    int t = threadIdx.x;
    const int CH = (NN + 1023) / 1024;
    int b = t * CH;
    int e = min(b + CH, NN);
    int s = 0;
    for (int i = b; i < e; i++) s += g_deg[i];
    sums[t] = s;
    __syncthreads();
    for (int off = 1; off < 1024; off <<= 1) {
        int v = (t >= off) ? sums[t - off] : 0;
        __syncthreads();
        sums[t] += v;
        __syncthreads();
    }
    int run = sums[t] - s;
    for (int i = b; i < e; i++) { g_off[i] = run; run += g_deg[i]; }
    if (t == 1023) g_off[NN] = sums[1023];
}

__global__ void k_csr(const int* __restrict__ ei) {
    int i = blockIdx.x * blockDim.x + threadIdx.x;
    if (i < EE) {
        int src = ei[i];
        int dst = ei[EE + i];
        int pos = g_off[dst] + atomicAdd(&g_cnt[dst], 1);
        g_csr[pos] = src;
    }
}

__global__ void k_hproj(const float* __restrict__ h_mat,
                        const float* __restrict__ hsW, const float* __restrict__ hsb,
                        const float* __restrict__ hnW, const float* __restrict__ hnb) {
    int idx = blockIdx.x * blockDim.x + threadIdx.x;
    if (idx >= NN * 64) return;
    int n = idx >> 6, j = idx & 63;
    float s1 = hsb[j], s2 = hnb[j];
    const float* hm = h_mat + n * 8;
#pragma unroll
    for (int d = 0; d < 8; d++) {
        float v = hm[d];
        s1 += v * hsW[d * 64 + j];
        s2 += v * hnW[d * 64 + j];
    }
    g_hsub[idx] = s1;
    g_hneigh[idx] = s2;
}

// one block = 16 nodes of ONE type; 128 threads = output dims
__global__ __launch_bounds__(128) void k_proj(
        const float* __restrict__ xs,
        const float* __restrict__ subW, const float* __restrict__ subb,
        const float* __restrict__ neighW, const float* __restrict__ neighb) {
    const int t = blockIdx.y;
    const int cnt = g_tcount[t];
    const int base = blockIdx.x * 16;
    if (base >= cnt) return;
    const int m = min(16, cnt - base);

    __shared__ float sx[16][DDIM];
    __shared__ int nd[16];
    int tid = threadIdx.x;
    if (tid < 16) nd[tid] = (tid < m) ? g_bucket[t * NN + base + tid] : 0;
    __syncthreads();
#pragma unroll
    for (int i = 0; i < 16; i++)
        sx[i][tid] = (i < m) ? xs[nd[i] * DDIM + tid] : 0.f;
    __syncthreads();

    float aq[16], ak[16];
#pragma unroll
    for (int i = 0; i < 16; i++) { aq[i] = 0.f; ak[i] = 0.f; }

    const float* wq = subW + t * DDIM * DDIM + tid;
    const float* wk = neighW + t * DDIM * DDIM + tid;
    for (int d = 0; d < DDIM; d += 4) {
        float qw0 = __ldg(wq + (d + 0) * DDIM);
        float qw1 = __ldg(wq + (d + 1) * DDIM);
        float qw2 = __ldg(wq + (d + 2) * DDIM);
        float qw3 = __ldg(wq + (d + 3) * DDIM);
        float kw0 = __ldg(wk + (d + 0) * DDIM);
        float kw1 = __ldg(wk + (d + 1) * DDIM);
        float kw2 = __ldg(wk + (d + 2) * DDIM);
        float kw3 = __ldg(wk + (d + 3) * DDIM);
#pragma unroll
        for (int i = 0; i < 16; i++) {
            float4 xv = *(const float4*)&sx[i][d];   // LDS.128 broadcast
            aq[i] += xv.x * qw0 + xv.y * qw1 + xv.z * qw2 + xv.w * qw3;
            ak[i] += xv.x * kw0 + xv.y * kw1 + xv.z * kw2 + xv.w * kw3;
        }
    }
    float bq = subb[t * DDIM + tid], bk = neighb[t * DDIM + tid];
    for (int i = 0; i < m; i++) {
        g_q[nd[i] * DDIM + tid] = aq[i] + bq;
        g_k[nd[i] * DDIM + tid] = ak[i] + bk;
    }
}

// ---------------- fused attention + softmax + aggregate + gelu + LN ----------------
// one warp per dst node; lane owns 4 contiguous output dims (head = lane>>2)
__global__ __launch_bounds__(256) void k_edge(
        const int* __restrict__ ntype,
        const float* __restrict__ ratt, const float* __restrict__ rhatt,
        const float* __restrict__ gamma, const float* __restrict__ beta,
        float* __restrict__ out) {
    int warp = (blockIdx.x * blockDim.x + threadIdx.x) >> 5;
    int lane = threadIdx.x & 31;
    if (warp >= NN) return;
    const int n = warp;
    const int h = lane >> 2;
    const int qd = lane & 3;
    const int st = ntype[n];

    const float4 qv = *(const float4*)(g_q + n * DDIM + lane * 4);
    const float2 hs = *(const float2*)(g_hsub + n * 64 + h * 8 + qd * 2);
    const float4 rv = *(const float4*)(ratt + (st * HH + h) * DKV + qd * 4);
    const float2 rh = *(const float2*)(rhatt + (st * HH + h) * HDV + qd * 2);

    const int b = g_off[n], e_end = g_off[n + 1];
    float a0 = 0.f, a1 = 0.f, a2 = 0.f, a3 = 0.f, den = 0.f;

    for (int p = b; p < e_end; p++) {
        int src = g_csr[p];
        float4 kv = *(const float4*)(g_k + src * DDIM + lane * 4);
        float2 hn = *(const float2*)(g_hneigh + src * 64 + h * 8 + qd * 2);

        float s1 = ftanh(qv.x * kv.x) * rv.x + ftanh(qv.y * kv.y) * rv.y
                 + ftanh(qv.z * kv.z) * rv.z + ftanh(qv.w * kv.w) * rv.w;
        s1 += __shfl_xor_sync(0xffffffffu, s1, 1);
        s1 += __shfl_xor_sync(0xffffffffu, s1, 2);

        float s2 = ftanh(hs.x * hn.x) * rh.x + ftanh(hs.y * hn.y) * rh.y;
        s2 += __shfl_xor_sync(0xffffffffu, s2, 1);
        s2 += __shfl_xor_sync(0xffffffffu, s2, 2);

        // att = (s1/4) * (s2/sqrt(8)); softmax weight w = exp(att)
        float w = __expf(s1 * 0.25f * s2 * 0.3535533905932738f);
        den += w;
        a0 += w * kv.x; a1 += w * kv.y; a2 += w * kv.z; a3 += w * kv.w;
    }

    float inv = __fdividef(1.f, den + 1e-16f);
    float g0 = gelu_exact(a0 * inv), g1 = gelu_exact(a1 * inv);
    float g2 = gelu_exact(a2 * inv), g3 = gelu_exact(a3 * inv);

    float s = g0 + g1 + g2 + g3;
#pragma unroll
    for (int o = 16; o; o >>= 1) s += __shfl_xor_sync(0xffffffffu, s, o);
    float mean = s * (1.0f / 128.0f);

    float d0 = g0 - mean, d1 = g1 - mean, d2 = g2 - mean, d3 = g3 - mean;
    float v = d0 * d0 + d1 * d1 + d2 * d2 + d3 * d3;
#pragma unroll
    for (int o = 16; o; o >>= 1) v += __shfl_xor_sync(0xffffffffu, v, o);
    float rs = rsqrtf(v * (1.0f / 128.0f) + 1e-5f);

    int d = lane * 4;
    float4 gm = *(const float4*)(gamma + d);
    float4 bt = *(const float4*)(beta + d);
    float4 ov;
    ov.x = d0 * rs * gm.x + bt.x;
    ov.y = d1 * rs * gm.y + bt.y;
    ov.z = d2 * rs * gm.z + bt.z;
    ov.w = d3 * rs * gm.w + bt.w;
    *(float4*)(out + n * DDIM + d) = ov;
}

// ---------------- launch ----------------
extern "C" void kernel_launch(void* const* d_in, const int* in_sizes, int n_in,
                              void* d_out, int out_size) {
    const float* meta_xs   = (const float*)d_in[0];
    const int*   node_type = (const int*)d_in[1];
    const int*   edge_idx  = (const int*)d_in[2];
    const float* h_mat     = (const float*)d_in[3];
    const float* sub_W     = (const float*)d_in[4];
    const float* sub_b     = (const float*)d_in[5];
    const float* neigh_W   = (const float*)d_in[6];
    const float* neigh_b   = (const float*)d_in[7];
    const float* hsub_W    = (const float*)d_in[8];
    const float* hsub_b    = (const float*)d_in[9];
    const float* hneigh_W  = (const float*)d_in[10];
    const float* hneigh_b  = (const float*)d_in[11];
    const float* rel_att   = (const float*)d_in[12];
    const float* rel_h_att = (const float*)d_in[13];
    const float* ln_gamma  = (const float*)d_in[14];
    const float* ln_beta   = (const float*)d_in[15];
    float* out = (float*)d_out;

    k_zero<<<(NN + 255) / 256, 256>>>();
    k_bucket_deg<<<(EE + 255) / 256, 256>>>(edge_idx, node_type);
    k_scan<<<1, 1024>>>();
    k_csr<<<(EE + 255) / 256, 256>>>(edge_idx);
    k_hproj<<<(NN * 64 + 255) / 256, 256>>>(h_mat, hsub_W, hsub_b, hneigh_W, hneigh_b);
    {
        dim3 grid((NN + 15) / 16, TT);
        k_proj<<<grid, 128>>>(meta_xs, sub_W, sub_b, neigh_W, neigh_b);
    }
    k_edge<<<(NN * 32 + 255) / 256, 256>>>(node_type, rel_att, rel_h_att,
                                           ln_gamma, ln_beta, out);
}

// round 3
// speedup vs baseline: 1.5823x; 1.0461x over previous
#include <cuda_runtime.h>
#include <math.h>

#define NN 50000
#define EE 800000
#define DDIM 128
#define TT 4
#define HH 8
#define DKV 16
#define HDV 8

#define PROJ_BX ((NN + 15) / 16)          // 3125
#define PROJ_BLOCKS (PROJ_BX * TT)        // 12500
#define CSR_BLOCKS ((EE + 127) / 128)     // 6250

// ---------------- scratch (static device memory; no allocation) ----------------
__device__ float g_q[NN * DDIM];
__device__ float g_k[NN * DDIM];
__device__ float g_hsub[NN * HH * HDV];
__device__ float g_hneigh[NN * HH * HDV];
__device__ int   g_deg[NN];
__device__ int   g_cnt[NN];
__device__ int   g_off[NN + 1];
__device__ int   g_csr[EE];          // stores SRC node id per CSR slot
__device__ int   g_bucket[TT * NN];
__device__ int   g_tcount[TT];

// ---------------- helpers ----------------
__device__ __forceinline__ float ftanh(float x) {
    float y;
    asm("tanh.approx.f32 %0, %1;" : "=f"(y) : "f"(x));
    return y;
}

__device__ __forceinline__ float gelu_exact(float x) {
    return 0.5f * x * (1.f + erff(x * 0.7071067811865475f));
}

// ---------------- fused: degree count + type bucketing + h projections ----------------
__global__ void k_pre(const int* __restrict__ ei, const int* __restrict__ ntype,
                      const float* __restrict__ h_mat,
                      const float* __restrict__ hsW, const float* __restrict__ hsb,
                      const float* __restrict__ hnW, const float* __restrict__ hnb) {
    int idx = blockIdx.x * blockDim.x + threadIdx.x;
    if (idx < NN * 64) {
        int n = idx >> 6, j = idx & 63;
        float s1 = hsb[j], s2 = hnb[j];
        const float* hm = h_mat + n * 8;
#pragma unroll
        for (int d = 0; d < 8; d++) {
            float v = hm[d];
            s1 += v * hsW[d * 64 + j];
            s2 += v * hnW[d * 64 + j];
        }
        g_hsub[idx] = s1;
        g_hneigh[idx] = s2;
    }
    if (idx < EE) atomicAdd(&g_deg[ei[EE + idx]], 1);
    if (idx < NN) {
        int t = ntype[idx];
        int p = atomicAdd(&g_tcount[t], 1);
        g_bucket[t * NN + p] = idx;
    }
}

__global__ void k_scan() {
    __shared__ int sums[1024];
    int t = threadIdx.x;
    const int CH = (NN + 1023) / 1024;
    int b = t * CH;
    int e = min(b + CH, NN);
    int s = 0;
    for (int i = b; i < e; i++) s += g_deg[i];
    sums[t] = s;
    __syncthreads();
    for (int off = 1; off < 1024; off <<= 1) {
        int v = (t >= off) ? sums[t - off] : 0;
        __syncthreads();
        sums[t] += v;
        __syncthreads();
    }
    int run = sums[t] - s;
    for (int i = b; i < e; i++) { g_off[i] = run; run += g_deg[i]; }
    if (t == 1023) g_off[NN] = sums[1023];
}

// ---------------- fused: CSR fill (first blocks) + type-bucketed q/k projection ----------------
__global__ __launch_bounds__(128) void k_mid(
        const float* __restrict__ xs,
        const float* __restrict__ subW, const float* __restrict__ subb,
        const float* __restrict__ neighW, const float* __restrict__ neighb,
        const int* __restrict__ ei) {
    const int blk = blockIdx.x;

    // ---- CSR-fill role (atomic-latency-bound; launched first to overlap with FMA blocks)
    if (blk < CSR_BLOCKS) {
        int i = blk * 128 + threadIdx.x;
        if (i < EE) {
            int src = ei[i];
            int dst = ei[EE + i];
            int pos = g_off[dst] + atomicAdd(&g_cnt[dst], 1);
            g_csr[pos] = src;
        }
        return;
    }

    // ---- projection role: one block = 16 nodes of ONE type; 128 threads = output dims
    const int pb = blk - CSR_BLOCKS;
    const int t = pb / PROJ_BX;
    const int base = (pb % PROJ_BX) * 16;
    const int cnt = g_tcount[t];
    if (base >= cnt) return;
    const int m = min(16, cnt - base);

    __shared__ float sx[16][DDIM];
    __shared__ int nd[16];
    int tid = threadIdx.x;
    if (tid < 16) nd[tid] = (tid < m) ? g_bucket[t * NN + base + tid] : 0;
    __syncthreads();
#pragma unroll
    for (int i = 0; i < 16; i++)
        sx[i][tid] = (i < m) ? xs[nd[i] * DDIM + tid] : 0.f;
    __syncthreads();

    float aq[16], ak[16];
#pragma unroll
    for (int i = 0; i < 16; i++) { aq[i] = 0.f; ak[i] = 0.f; }

    const float* wq = subW + t * DDIM * DDIM + tid;
    const float* wk = neighW + t * DDIM * DDIM + tid;
    for (int d = 0; d < DDIM; d += 4) {
        float qw0 = __ldg(wq + (d + 0) * DDIM);
        float qw1 = __ldg(wq + (d + 1) * DDIM);
        float qw2 = __ldg(wq + (d + 2) * DDIM);
        float qw3 = __ldg(wq + (d + 3) * DDIM);
        float kw0 = __ldg(wk + (d + 0) * DDIM);
        float kw1 = __ldg(wk + (d + 1) * DDIM);
        float kw2 = __ldg(wk + (d + 2) * DDIM);
        float kw3 = __ldg(wk + (d + 3) * DDIM);
#pragma unroll
        for (int i = 0; i < 16; i++) {
            float4 xv = *(const float4*)&sx[i][d];   // LDS.128 broadcast
            aq[i] += xv.x * qw0 + xv.y * qw1 + xv.z * qw2 + xv.w * qw3;
            ak[i] += xv.x * kw0 + xv.y * kw1 + xv.z * kw2 + xv.w * kw3;
        }
    }
    float bq = subb[t * DDIM + tid], bk = neighb[t * DDIM + tid];
    for (int i = 0; i < m; i++) {
        g_q[nd[i] * DDIM + tid] = aq[i] + bq;
        g_k[nd[i] * DDIM + tid] = ak[i] + bk;
    }
}

// ---------------- fused attention + softmax + aggregate + gelu + LN ----------------
// one warp per dst node; lane owns 4 contiguous output dims (head = lane>>2)
__global__ __launch_bounds__(256) void k_edge(
        const int* __restrict__ ntype,
        const float* __restrict__ ratt, const float* __restrict__ rhatt,
        const float* __restrict__ gamma, const float* __restrict__ beta,
        float* __restrict__ out) {
    int warp = (blockIdx.x * blockDim.x + threadIdx.x) >> 5;
    int lane = threadIdx.x & 31;
    if (warp >= NN) return;
    const int n = warp;
    const int h = lane >> 2;
    const int qd = lane & 3;
    const int st = ntype[n];
    const float C = 0.08838834764831845f;   // 1/(4*sqrt(8))

    const float4 qv = *(const float4*)(g_q + n * DDIM + lane * 4);
    const float2 hs = *(const float2*)(g_hsub + n * 64 + h * 8 + qd * 2);
    const float4 rv = *(const float4*)(ratt + (st * HH + h) * DKV + qd * 4);
    const float2 rh = *(const float2*)(rhatt + (st * HH + h) * HDV + qd * 2);

    const int b = g_off[n], e_end = g_off[n + 1];
    float a0 = 0.f, a1 = 0.f, a2 = 0.f, a3 = 0.f, den = 0.f;

    int p = b;
    for (; p + 2 <= e_end; p += 2) {
        int s0 = g_csr[p];
        int s1i = g_csr[p + 1];
        float4 kv0 = *(const float4*)(g_k + s0 * DDIM + lane * 4);
        float4 kv1 = *(const float4*)(g_k + s1i * DDIM + lane * 4);
        float2 hn0 = *(const float2*)(g_hneigh + s0 * 64 + h * 8 + qd * 2);
        float2 hn1 = *(const float2*)(g_hneigh + s1i * 64 + h * 8 + qd * 2);

        float sa0 = ftanh(qv.x * kv0.x) * rv.x + ftanh(qv.y * kv0.y) * rv.y
                  + ftanh(qv.z * kv0.z) * rv.z + ftanh(qv.w * kv0.w) * rv.w;
        float sa1 = ftanh(qv.x * kv1.x) * rv.x + ftanh(qv.y * kv1.y) * rv.y
                  + ftanh(qv.z * kv1.z) * rv.z + ftanh(qv.w * kv1.w) * rv.w;
        float sb0 = ftanh(hs.x * hn0.x) * rh.x + ftanh(hs.y * hn0.y) * rh.y;
        float sb1 = ftanh(hs.x * hn1.x) * rh.x + ftanh(hs.y * hn1.y) * rh.y;

        sa0 += __shfl_xor_sync(0xffffffffu, sa0, 1);
        sa1 += __shfl_xor_sync(0xffffffffu, sa1, 1);
        sb0 += __shfl_xor_sync(0xffffffffu, sb0, 1);
        sb1 += __shfl_xor_sync(0xffffffffu, sb1, 1);
        sa0 += __shfl_xor_sync(0xffffffffu, sa0, 2);
        sa1 += __shfl_xor_sync(0xffffffffu, sa1, 2);
        sb0 += __shfl_xor_sync(0xffffffffu, sb0, 2);
        sb1 += __shfl_xor_sync(0xffffffffu, sb1, 2);

        float w0 = __expf(sa0 * sb0 * C);
        float w1 = __expf(sa1 * sb1 * C);
        den += w0 + w1;
        a0 += w0 * kv0.x + w1 * kv1.x;
        a1 += w0 * kv0.y + w1 * kv1.y;
        a2 += w0 * kv0.z + w1 * kv1.z;
        a3 += w0 * kv0.w + w1 * kv1.w;
    }
    if (p < e_end) {
        int s0 = g_csr[p];
        float4 kv0 = *(const float4*)(g_k + s0 * DDIM + lane * 4);
        float2 hn0 = *(const float2*)(g_hneigh + s0 * 64 + h * 8 + qd * 2);

        float sa0 = ftanh(qv.x * kv0.x) * rv.x + ftanh(qv.y * kv0.y) * rv.y
                  + ftanh(qv.z * kv0.z) * rv.z + ftanh(qv.w * kv0.w) * rv.w;
        float sb0 = ftanh(hs.x * hn0.x) * rh.x + ftanh(hs.y * hn0.y) * rh.y;
        sa0 += __shfl_xor_sync(0xffffffffu, sa0, 1);
        sb0 += __shfl_xor_sync(0xffffffffu, sb0, 1);
        sa0 += __shfl_xor_sync(0xffffffffu, sa0, 2);
        sb0 += __shfl_xor_sync(0xffffffffu, sb0, 2);

        float w0 = __expf(sa0 * sb0 * C);
        den += w0;
        a0 += w0 * kv0.x; a1 += w0 * kv0.y; a2 += w0 * kv0.z; a3 += w0 * kv0.w;
    }

    float inv = __fdividef(1.f, den + 1e-16f);
    float g0 = gelu_exact(a0 * inv), g1 = gelu_exact(a1 * inv);
    float g2 = gelu_exact(a2 * inv), g3 = gelu_exact(a3 * inv);

    float s = g0 + g1 + g2 + g3;
#pragma unroll
    for (int o = 16; o; o >>= 1) s += __shfl_xor_sync(0xffffffffu, s, o);
    float mean = s * (1.0f / 128.0f);

    float d0 = g0 - mean, d1 = g1 - mean, d2 = g2 - mean, d3 = g3 - mean;
    float v = d0 * d0 + d1 * d1 + d2 * d2 + d3 * d3;
#pragma unroll
    for (int o = 16; o; o >>= 1) v += __shfl_xor_sync(0xffffffffu, v, o);
    float rs = rsqrtf(v * (1.0f / 128.0f) + 1e-5f);

    int d = lane * 4;
    float4 gm = *(const float4*)(gamma + d);
    float4 bt = *(const float4*)(beta + d);
    float4 ov;
    ov.x = d0 * rs * gm.x + bt.x;
    ov.y = d1 * rs * gm.y + bt.y;
    ov.z = d2 * rs * gm.z + bt.z;
    ov.w = d3 * rs * gm.w + bt.w;
    *(float4*)(out + n * DDIM + d) = ov;
}

// ---------------- launch ----------------
extern "C" void kernel_launch(void* const* d_in, const int* in_sizes, int n_in,
                              void* d_out, int out_size) {
    const float* meta_xs   = (const float*)d_in[0];
    const int*   node_type = (const int*)d_in[1];
    const int*   edge_idx  = (const int*)d_in[2];
    const float* h_mat     = (const float*)d_in[3];
    const float* sub_W     = (const float*)d_in[4];
    const float* sub_b     = (const float*)d_in[5];
    const float* neigh_W   = (const float*)d_in[6];
    const float* neigh_b   = (const float*)d_in[7];
    const float* hsub_W    = (const float*)d_in[8];
    const float* hsub_b    = (const float*)d_in[9];
    const float* hneigh_W  = (const float*)d_in[10];
    const float* hneigh_b  = (const float*)d_in[11];
    const float* rel_att   = (const float*)d_in[12];
    const float* rel_h_att = (const float*)d_in[13];
    const float* ln_gamma  = (const float*)d_in[14];
    const float* ln_beta   = (const float*)d_in[15];
    float* out = (float*)d_out;

    void *p_deg, *p_cnt, *p_tc;
    cudaGetSymbolAddress(&p_deg, g_deg);
    cudaGetSymbolAddress(&p_cnt, g_cnt);
    cudaGetSymbolAddress(&p_tc,  g_tcount);
    cudaMemsetAsync(p_deg, 0, NN * sizeof(int));
    cudaMemsetAsync(p_cnt, 0, NN * sizeof(int));
    cudaMemsetAsync(p_tc,  0, TT * sizeof(int));

    k_pre<<<(NN * 64 + 255) / 256, 256>>>(edge_idx, node_type, h_mat,
                                          hsub_W, hsub_b, hneigh_W, hneigh_b);
    k_scan<<<1, 1024>>>();
    k_mid<<<CSR_BLOCKS + PROJ_BLOCKS, 128>>>(meta_xs, sub_W, sub_b,
                                             neigh_W, neigh_b, edge_idx);
    k_edge<<<(NN * 32 + 255) / 256, 256>>>(node_type, rel_att, rel_h_att,
                                           ln_gamma, ln_beta, out);
}

// round 4
// speedup vs baseline: 1.6600x; 1.0491x over previous
#include <cuda_runtime.h>
#include <math.h>

#define NN 50000
#define EE 800000
#define DDIM 128
#define TT 4
#define HH 8
#define DKV 16
#define HDV 8

#define PROJ_BX ((NN + 15) / 16)          // 3125
#define PROJ_BLOCKS (PROJ_BX * TT)        // 12500
#define CSR_BLOCKS ((EE + 127) / 128)     // 6250

typedef unsigned long long u64;

// ---------------- scratch (static device memory; no allocation) ----------------
__device__ float g_q[NN * DDIM];
__device__ float g_k[NN * DDIM];
__device__ float g_hsub[NN * HH * HDV];
__device__ float g_hneigh[NN * HH * HDV];
__device__ int   g_deg[NN];
__device__ int   g_cnt[NN];
__device__ int   g_off[NN + 1];
__device__ int   g_csr[EE];          // SRC node id per CSR slot
__device__ int   g_bucket[TT * NN];
__device__ int   g_tcount[TT];

// ---------------- helpers ----------------
__device__ __forceinline__ float ftanh(float x) {
    float y;
    asm("tanh.approx.f32 %0, %1;" : "=f"(y) : "f"(x));
    return y;
}
__device__ __forceinline__ float gelu_exact(float x) {
    return 0.5f * x * (1.f + erff(x * 0.7071067811865475f));
}
__device__ __forceinline__ u64 pack2(float lo, float hi) {
    u64 r; asm("mov.b64 %0, {%1, %2};" : "=l"(r) : "f"(lo), "f"(hi)); return r;
}
__device__ __forceinline__ void unpack2(u64 v, float& lo, float& hi) {
    asm("mov.b64 {%0, %1}, %2;" : "=f"(lo), "=f"(hi) : "l"(v));
}
__device__ __forceinline__ u64 ffma2(u64 a, u64 b, u64 c) {
    u64 d; asm("fma.rn.f32x2 %0, %1, %2, %3;" : "=l"(d) : "l"(a), "l"(b), "l"(c)); return d;
}

// ---------------- fused: degree count + type bucketing + h projections ----------------
__global__ void k_pre(const int* __restrict__ ei, const int* __restrict__ ntype,
                      const float* __restrict__ h_mat,
                      const float* __restrict__ hsW, const float* __restrict__ hsb,
                      const float* __restrict__ hnW, const float* __restrict__ hnb) {
    int idx = blockIdx.x * blockDim.x + threadIdx.x;
    if (idx < NN * 64) {
        int n = idx >> 6, j = idx & 63;
        float s1 = hsb[j], s2 = hnb[j];
        const float* hm = h_mat + n * 8;
#pragma unroll
        for (int d = 0; d < 8; d++) {
            float v = hm[d];
            s1 += v * hsW[d * 64 + j];
            s2 += v * hnW[d * 64 + j];
        }
        g_hsub[idx] = s1;
        g_hneigh[idx] = s2;
    }
    if (idx < EE) atomicAdd(&g_deg[ei[EE + idx]], 1);
    if (idx < NN) {
        int t = ntype[idx];
        int p = atomicAdd(&g_tcount[t], 1);
        g_bucket[t * NN + p] = idx;
    }
}

__global__ void k_scan() {
    __shared__ int sums[1024];
    int t = threadIdx.x;
    const int CH = (NN + 1023) / 1024;
    int b = t * CH;
    int e = min(b + CH, NN);
    int s = 0;
    for (int i = b; i < e; i++) s += g_deg[i];
    sums[t] = s;
    __syncthreads();
    for (int off = 1; off < 1024; off <<= 1) {
        int v = (t >= off) ? sums[t - off] : 0;
        __syncthreads();
        sums[t] += v;
        __syncthreads();
    }
    int run = sums[t] - s;
    for (int i = b; i < e; i++) { g_off[i] = run; run += g_deg[i]; }
    if (t == 1023) g_off[NN] = sums[1023];
}

// ---------------- fused: CSR fill + type-bucketed q/k projection (FFMA2) ----------------
__global__ __launch_bounds__(128) void k_mid(
        const float* __restrict__ xs,
        const float* __restrict__ subW, const float* __restrict__ subb,
        const float* __restrict__ neighW, const float* __restrict__ neighb,
        const int* __restrict__ ei) {
    const int blk = blockIdx.x;

    // ---- CSR-fill role (atomic-latency-bound; overlaps with FMA blocks)
    if (blk < CSR_BLOCKS) {
        int i = blk * 128 + threadIdx.x;
        if (i < EE) {
            int src = ei[i];
            int dst = ei[EE + i];
            int pos = g_off[dst] + atomicAdd(&g_cnt[dst], 1);
            g_csr[pos] = src;
        }
        return;
    }

    // ---- projection role: one block = 16 nodes of ONE type; 128 threads = output dims
    const int pb = blk - CSR_BLOCKS;
    const int t = pb / PROJ_BX;
    const int base = (pb % PROJ_BX) * 16;
    const int cnt = g_tcount[t];
    if (base >= cnt) return;
    const int m = min(16, cnt - base);

    // transposed x tile: sxp[d][node], stride 20 floats (16B-aligned rows, 4-way
    // write conflicts only on the fill)
    __shared__ float sxp[DDIM][20];
    __shared__ int nd[16];
    int tid = threadIdx.x;
    if (tid < 16) nd[tid] = (tid < m) ? g_bucket[t * NN + base + tid] : 0;
    __syncthreads();
#pragma unroll
    for (int i = 0; i < 16; i++)
        sxp[tid][i] = (i < m) ? xs[nd[i] * DDIM + tid] : 0.f;
    __syncthreads();

    u64 aq[8], ak[8];
#pragma unroll
    for (int i = 0; i < 8; i++) { aq[i] = 0ULL; ak[i] = 0ULL; }

    const float* wq = subW + t * DDIM * DDIM + tid;
    const float* wk = neighW + t * DDIM * DDIM + tid;
    for (int d = 0; d < DDIM; d++) {
        float qw = __ldg(wq + d * DDIM);
        float kw = __ldg(wk + d * DDIM);
        u64 qw2 = pack2(qw, qw);
        u64 kw2 = pack2(kw, kw);
#pragma unroll
        for (int j = 0; j < 4; j++) {
            ulonglong2 xv = *(const ulonglong2*)&sxp[d][j * 4];   // LDS.128: 2 node-pairs
            aq[j * 2 + 0] = ffma2(xv.x, qw2, aq[j * 2 + 0]);
            aq[j * 2 + 1] = ffma2(xv.y, qw2, aq[j * 2 + 1]);
            ak[j * 2 + 0] = ffma2(xv.x, kw2, ak[j * 2 + 0]);
            ak[j * 2 + 1] = ffma2(xv.y, kw2, ak[j * 2 + 1]);
        }
    }
    float bq = subb[t * DDIM + tid], bk = neighb[t * DDIM + tid];
#pragma unroll
    for (int j = 0; j < 8; j++) {
        float qlo, qhi, klo, khi;
        unpack2(aq[j], qlo, qhi);
        unpack2(ak[j], klo, khi);
        int i0 = j * 2, i1 = j * 2 + 1;
        if (i0 < m) { g_q[nd[i0] * DDIM + tid] = qlo + bq; g_k[nd[i0] * DDIM + tid] = klo + bk; }
        if (i1 < m) { g_q[nd[i1] * DDIM + tid] = qhi + bq; g_k[nd[i1] * DDIM + tid] = khi + bk; }
    }
}

// ---------------- fused attention + softmax + aggregate + gelu + LN ----------------
// one warp per dst node; 16 lanes per edge, two edges in flight (half-warps)
// lane: half=lane>>4, l=lane&15, head=l>>1, qd=l&1; lane owns 8 dims h*16+qd*8
__global__ __launch_bounds__(256) void k_edge(
        const int* __restrict__ ntype,
        const float* __restrict__ ratt, const float* __restrict__ rhatt,
        const float* __restrict__ gamma, const float* __restrict__ beta,
        float* __restrict__ out) {
    int warp = (blockIdx.x * blockDim.x + threadIdx.x) >> 5;
    int lane = threadIdx.x & 31;
    if (warp >= NN) return;
    const int n = warp;
    const int half = lane >> 4;
    const int l = lane & 15;
    const int h = l >> 1;
    const int qd = l & 1;
    const unsigned hmask = half ? 0xFFFF0000u : 0x0000FFFFu;
    const int st = ntype[n];
    const float C = 0.08838834764831845f;   // 1/(4*sqrt(8))

    const float* qp = g_q + n * DDIM + h * 16 + qd * 8;
    const float4 qv0 = *(const float4*)qp;
    const float4 qv1 = *(const float4*)(qp + 4);
    const float* rp = ratt + (st * HH + h) * DKV + qd * 8;
    const float4 rv0 = *(const float4*)rp;
    const float4 rv1 = *(const float4*)(rp + 4);
    const float4 hs = *(const float4*)(g_hsub + n * 64 + h * 8 + qd * 4);
    const float4 rh = *(const float4*)(rhatt + (st * HH + h) * HDV + qd * 4);

    const int b = g_off[n], e_end = g_off[n + 1];
    float a0 = 0.f, a1 = 0.f, a2 = 0.f, a3 = 0.f;
    float a4 = 0.f, a5 = 0.f, a6 = 0.f, a7 = 0.f, den = 0.f;

    for (int p = b + half; p < e_end; p += 2) {
        int src = g_csr[p];
        const float* kp = g_k + src * DDIM + h * 16 + qd * 8;
        float4 kv0 = *(const float4*)kp;
        float4 kv1 = *(const float4*)(kp + 4);
        float4 hn = *(const float4*)(g_hneigh + src * 64 + h * 8 + qd * 4);

        float sa = ftanh(qv0.x * kv0.x) * rv0.x + ftanh(qv0.y * kv0.y) * rv0.y
                 + ftanh(qv0.z * kv0.z) * rv0.z + ftanh(qv0.w * kv0.w) * rv0.w
                 + ftanh(qv1.x * kv1.x) * rv1.x + ftanh(qv1.y * kv1.y) * rv1.y
                 + ftanh(qv1.z * kv1.z) * rv1.z + ftanh(qv1.w * kv1.w) * rv1.w;
        float sb = ftanh(hs.x * hn.x) * rh.x + ftanh(hs.y * hn.y) * rh.y
                 + ftanh(hs.z * hn.z) * rh.z + ftanh(hs.w * hn.w) * rh.w;

        sa += __shfl_xor_sync(hmask, sa, 1);
        sb += __shfl_xor_sync(hmask, sb, 1);

        float w = __expf(sa * sb * C);
        den += w;
        a0 += w * kv0.x; a1 += w * kv0.y; a2 += w * kv0.z; a3 += w * kv0.w;
        a4 += w * kv1.x; a5 += w * kv1.y; a6 += w * kv1.z; a7 += w * kv1.w;
    }

    // combine the two half-warps (same dims, different edge subsets)
    __syncwarp();
    a0 += __shfl_xor_sync(0xffffffffu, a0, 16);
    a1 += __shfl_xor_sync(0xffffffffu, a1, 16);
    a2 += __shfl_xor_sync(0xffffffffu, a2, 16);
    a3 += __shfl_xor_sync(0xffffffffu, a3, 16);
    a4 += __shfl_xor_sync(0xffffffffu, a4, 16);
    a5 += __shfl_xor_sync(0xffffffffu, a5, 16);
    a6 += __shfl_xor_sync(0xffffffffu, a6, 16);
    a7 += __shfl_xor_sync(0xffffffffu, a7, 16);
    den += __shfl_xor_sync(0xffffffffu, den, 16);

    if (half) return;   // lanes 0..15 own all 128 dims; finish there

    float inv = __fdividef(1.f, den + 1e-16f);
    float g0 = gelu_exact(a0 * inv), g1 = gelu_exact(a1 * inv);
    float g2 = gelu_exact(a2 * inv), g3 = gelu_exact(a3 * inv);
    float g4 = gelu_exact(a4 * inv), g5 = gelu_exact(a5 * inv);
    float g6 = gelu_exact(a6 * inv), g7 = gelu_exact(a7 * inv);

    float s = g0 + g1 + g2 + g3 + g4 + g5 + g6 + g7;
#pragma unroll
    for (int o = 8; o; o >>= 1) s += __shfl_xor_sync(0x0000FFFFu, s, o);
    float mean = s * (1.0f / 128.0f);

    float d0 = g0 - mean, d1 = g1 - mean, d2 = g2 - mean, d3 = g3 - mean;
    float d4 = g4 - mean, d5 = g5 - mean, d6 = g6 - mean, d7 = g7 - mean;
    float v = d0 * d0 + d1 * d1 + d2 * d2 + d3 * d3
            + d4 * d4 + d5 * d5 + d6 * d6 + d7 * d7;
#pragma unroll
    for (int o = 8; o; o >>= 1) v += __shfl_xor_sync(0x0000FFFFu, v, o);
    float rs = rsqrtf(v * (1.0f / 128.0f) + 1e-5f);

    int d = h * 16 + qd * 8;
    const float4 gm0 = *(const float4*)(gamma + d);
    const float4 gm1 = *(const float4*)(gamma + d + 4);
    const float4 bt0 = *(const float4*)(beta + d);
    const float4 bt1 = *(const float4*)(beta + d + 4);
    float4 o0, o1;
    o0.x = d0 * rs * gm0.x + bt0.x;
    o0.y = d1 * rs * gm0.y + bt0.y;
    o0.z = d2 * rs * gm0.z + bt0.z;
    o0.w = d3 * rs * gm0.w + bt0.w;
    o1.x = d4 * rs * gm1.x + bt1.x;
    o1.y = d5 * rs * gm1.y + bt1.y;
    o1.z = d6 * rs * gm1.z + bt1.z;
    o1.w = d7 * rs * gm1.w + bt1.w;
    *(float4*)(out + n * DDIM + d) = o0;
    *(float4*)(out + n * DDIM + d + 4) = o1;
}

// ---------------- launch ----------------
extern "C" void kernel_launch(void* const* d_in, const int* in_sizes, int n_in,
                              void* d_out, int out_size) {
    const float* meta_xs   = (const float*)d_in[0];
    const int*   node_type = (const int*)d_in[1];
    const int*   edge_idx  = (const int*)d_in[2];
    const float* h_mat     = (const float*)d_in[3];
    const float* sub_W     = (const float*)d_in[4];
    const float* sub_b     = (const float*)d_in[5];
    const float* neigh_W   = (const float*)d_in[6];
    const float* neigh_b   = (const float*)d_in[7];
    const float* hsub_W    = (const float*)d_in[8];
    const float* hsub_b    = (const float*)d_in[9];
    const float* hneigh_W  = (const float*)d_in[10];
    const float* hneigh_b  = (const float*)d_in[11];
    const float* rel_att   = (const float*)d_in[12];
    const float* rel_h_att = (const float*)d_in[13];
    const float* ln_gamma  = (const float*)d_in[14];
    const float* ln_beta   = (const float*)d_in[15];
    float* out = (float*)d_out;

    void *p_deg, *p_cnt, *p_tc;
    cudaGetSymbolAddress(&p_deg, g_deg);
    cudaGetSymbolAddress(&p_cnt, g_cnt);
    cudaGetSymbolAddress(&p_tc,  g_tcount);
    cudaMemsetAsync(p_deg, 0, NN * sizeof(int));
    cudaMemsetAsync(p_cnt, 0, NN * sizeof(int));
    cudaMemsetAsync(p_tc,  0, TT * sizeof(int));

    k_pre<<<(NN * 64 + 255) / 256, 256>>>(edge_idx, node_type, h_mat,
                                          hsub_W, hsub_b, hneigh_W, hneigh_b);
    k_scan<<<1, 1024>>>();
    k_mid<<<CSR_BLOCKS + PROJ_BLOCKS, 128>>>(meta_xs, sub_W, sub_b,
                                             neigh_W, neigh_b, edge_idx);
    k_edge<<<(NN * 32 + 255) / 256, 256>>>(node_type, rel_att, rel_h_att,
                                           ln_gamma, ln_beta, out);
}

// round 5
// speedup vs baseline: 1.6811x; 1.0127x over previous
#include <cuda_runtime.h>
#include <math.h>

#define NN 50000
#define EE 800000
#define DDIM 128
#define TT 4
#define HH 8
#define DKV 16
#define HDV 8

#define CSR_BLOCKS ((EE + 127) / 128)        // 6250
#define PROJ_BX ((NN + 31) / 32)             // 1563
#define PROJ_BLOCKS (PROJ_BX * TT)           // 6252
#define HPROJ_BLOCKS ((NN * 64 + 1023) / 1024)  // 3125

typedef unsigned long long u64;

// ---------------- scratch (static device memory; no allocation) ----------------
__device__ float g_q[NN * DDIM];
__device__ float g_k[NN * DDIM];
__device__ float g_hsub[NN * HH * HDV];
__device__ float g_hneigh[NN * HH * HDV];
__device__ int   g_zeroed[2 * NN + TT];      // [deg | cnt | tcount] one memset
#define G_DEG(i) g_zeroed[i]
#define G_CNT(i) g_zeroed[NN + (i)]
#define G_TC(i)  g_zeroed[2 * NN + (i)]
__device__ int   g_off[NN + 1];
__device__ int   g_csr[EE];                  // BYTE offset src*512 per CSR slot
__device__ int   g_bucket[TT * NN];

// ---------------- helpers ----------------
__device__ __forceinline__ float ftanh(float x) {
    float y;
    asm("tanh.approx.f32 %0, %1;" : "=f"(y) : "f"(x));
    return y;
}
__device__ __forceinline__ float gelu_exact(float x) {
    return 0.5f * x * (1.f + erff(x * 0.7071067811865475f));
}
__device__ __forceinline__ u64 pack2(float lo, float hi) {
    u64 r; asm("mov.b64 %0, {%1, %2};" : "=l"(r) : "f"(lo), "f"(hi)); return r;
}
__device__ __forceinline__ void unpack2(u64 v, float& lo, float& hi) {
    asm("mov.b64 {%0, %1}, %2;" : "=f"(lo), "=f"(hi) : "l"(v));
}
__device__ __forceinline__ u64 ffma2(u64 a, u64 b, u64 c) {
    u64 d; asm("fma.rn.f32x2 %0, %1, %2, %3;" : "=l"(d) : "l"(a), "l"(b), "l"(c)); return d;
}

// ---------------- A: degree count + type bucketing (smem-aggregated) ----------------
__global__ void k_preA(const int* __restrict__ ei, const int* __restrict__ ntype) {
    __shared__ int s_cnt[TT], s_base[TT];
    int idx = blockIdx.x * blockDim.x + threadIdx.x;
    if (threadIdx.x < TT) s_cnt[threadIdx.x] = 0;
    __syncthreads();

    if (idx < EE) atomicAdd(&G_DEG(ei[EE + idx]), 1);

    int t = -1, pos = 0;
    if (idx < NN) {
        t = ntype[idx];
        pos = atomicAdd(&s_cnt[t], 1);
    }
    __syncthreads();
    if (threadIdx.x < TT && s_cnt[threadIdx.x] > 0)
        s_base[threadIdx.x] = atomicAdd(&G_TC(threadIdx.x), s_cnt[threadIdx.x]);
    __syncthreads();
    if (idx < NN) g_bucket[t * NN + s_base[t] + pos] = idx;
}

// ---------------- B: scan (block 0) + h projections (other blocks) ----------------
__global__ __launch_bounds__(1024) void k_preB(
        const float* __restrict__ h_mat,
        const float* __restrict__ hsW, const float* __restrict__ hsb,
        const float* __restrict__ hnW, const float* __restrict__ hnb) {
    if (blockIdx.x == 0) {
        // single-block prefix scan of degrees
        __shared__ int sums[1024];
        int t = threadIdx.x;
        const int CH = (NN + 1023) / 1024;
        int b = t * CH;
        int e = min(b + CH, NN);
        int s = 0;
        for (int i = b; i < e; i++) s += G_DEG(i);
        sums[t] = s;
        __syncthreads();
        for (int off = 1; off < 1024; off <<= 1) {
            int v = (t >= off) ? sums[t - off] : 0;
            __syncthreads();
            sums[t] += v;
            __syncthreads();
        }
        int run = sums[t] - s;
        for (int i = b; i < e; i++) { g_off[i] = run; run += G_DEG(i); }
        if (t == 1023) g_off[NN] = sums[1023];
        return;
    }
    int idx = (blockIdx.x - 1) * 1024 + threadIdx.x;
    if (idx >= NN * 64) return;
    int n = idx >> 6, j = idx & 63;
    float s1 = hsb[j], s2 = hnb[j];
    const float* hm = h_mat + n * 8;
#pragma unroll
    for (int d = 0; d < 8; d++) {
        float v = hm[d];
        s1 += v * hsW[d * 64 + j];
        s2 += v * hnW[d * 64 + j];
    }
    g_hsub[idx] = s1;
    g_hneigh[idx] = s2;
}

// ---------------- fused: CSR fill + type-bucketed q/k projection (FFMA2, 32 nodes) ----------------
__global__ __launch_bounds__(128) void k_mid(
        const float* __restrict__ xs,
        const float* __restrict__ subW, const float* __restrict__ subb,
        const float* __restrict__ neighW, const float* __restrict__ neighb,
        const int* __restrict__ ei) {
    const int blk = blockIdx.x;

    // ---- CSR-fill role (atomic-latency-bound; overlaps with FMA blocks)
    if (blk < CSR_BLOCKS) {
        int i = blk * 128 + threadIdx.x;
        if (i < EE) {
            int src = ei[i];
            int dst = ei[EE + i];
            int pos = g_off[dst] + atomicAdd(&G_CNT(dst), 1);
            g_csr[pos] = src * 512;          // byte offset into g_k
        }
        return;
    }

    // ---- projection role: one block = 32 nodes of ONE type; 128 threads = output dims
    const int pb = blk - CSR_BLOCKS;
    const int t = pb / PROJ_BX;
    const int base = (pb % PROJ_BX) * 32;
    const int cnt = G_TC(t);
    if (base >= cnt) return;
    const int m = min(32, cnt - base);

    // transposed x tile: sxp[d][node], stride 36 floats (16B-aligned rows)
    __shared__ float sxp[DDIM][36];
    __shared__ int nd[32];
    int tid = threadIdx.x;
    if (tid < 32) nd[tid] = (tid < m) ? g_bucket[t * NN + base + tid] : 0;
    __syncthreads();
#pragma unroll
    for (int i = 0; i < 32; i++)
        sxp[tid][i] = (i < m) ? xs[nd[i] * DDIM + tid] : 0.f;
    __syncthreads();

    u64 aq[16], ak[16];
#pragma unroll
    for (int i = 0; i < 16; i++) { aq[i] = 0ULL; ak[i] = 0ULL; }

    const float* wq = subW + t * DDIM * DDIM + tid;
    const float* wk = neighW + t * DDIM * DDIM + tid;
    for (int d = 0; d < DDIM; d++) {
        float qw = __ldg(wq + d * DDIM);
        float kw = __ldg(wk + d * DDIM);
        u64 qw2 = pack2(qw, qw);
        u64 kw2 = pack2(kw, kw);
#pragma unroll
        for (int j = 0; j < 8; j++) {
            ulonglong2 xv = *(const ulonglong2*)&sxp[d][j * 4];  // broadcast LDS.128
            aq[j * 2 + 0] = ffma2(xv.x, qw2, aq[j * 2 + 0]);
            aq[j * 2 + 1] = ffma2(xv.y, qw2, aq[j * 2 + 1]);
            ak[j * 2 + 0] = ffma2(xv.x, kw2, ak[j * 2 + 0]);
            ak[j * 2 + 1] = ffma2(xv.y, kw2, ak[j * 2 + 1]);
        }
    }
    float bq = subb[t * DDIM + tid], bk = neighb[t * DDIM + tid];
#pragma unroll
    for (int j = 0; j < 16; j++) {
        float qlo, qhi, klo, khi;
        unpack2(aq[j], qlo, qhi);
        unpack2(ak[j], klo, khi);
        int i0 = j * 2, i1 = j * 2 + 1;
        if (i0 < m) { g_q[nd[i0] * DDIM + tid] = qlo + bq; g_k[nd[i0] * DDIM + tid] = klo + bk; }
        if (i1 < m) { g_q[nd[i1] * DDIM + tid] = qhi + bq; g_k[nd[i1] * DDIM + tid] = khi + bk; }
    }
}

// ---------------- fused attention + softmax + aggregate + gelu + LN ----------------
// one warp per dst node; lane owns 4 contiguous output dims (head = lane>>2)
__global__ __launch_bounds__(256, 6) void k_edge(
        const int* __restrict__ ntype,
        const float* __restrict__ ratt, const float* __restrict__ rhatt,
        const float* __restrict__ gamma, const float* __restrict__ beta,
        float* __restrict__ out) {
    int warp = (blockIdx.x * blockDim.x + threadIdx.x) >> 5;
    int lane = threadIdx.x & 31;
    if (warp >= NN) return;
    const int n = warp;
    const int h = lane >> 2;
    const int qd = lane & 3;
    const int st = ntype[n];
    const float C = 0.08838834764831845f;   // 1/(4*sqrt(8))

    const float4 qv = *(const float4*)(g_q + n * DDIM + lane * 4);
    const float2 hs = *(const float2*)(g_hsub + n * 64 + h * 8 + qd * 2);
    const float4 rv = *(const float4*)(ratt + (st * HH + h) * DKV + qd * 4);
    const float2 rh = *(const float2*)(rhatt + (st * HH + h) * HDV + qd * 2);

    const char* kbase = (const char*)g_k + lane * 16;
    const char* hbase = (const char*)g_hneigh + (h * 8 + qd * 2) * 4;

    const int b = g_off[n], e_end = g_off[n + 1];
    float a0 = 0.f, a1 = 0.f, a2 = 0.f, a3 = 0.f, den = 0.f;

    int p = b;
    for (; p + 2 <= e_end; p += 2) {
        int o0 = g_csr[p];
        int o1 = g_csr[p + 1];
        float4 kv0 = *(const float4*)(kbase + o0);
        float4 kv1 = *(const float4*)(kbase + o1);
        float2 hn0 = *(const float2*)(hbase + (o0 >> 1));
        float2 hn1 = *(const float2*)(hbase + (o1 >> 1));

        float sa0 = ftanh(qv.x * kv0.x) * rv.x + ftanh(qv.y * kv0.y) * rv.y
                  + ftanh(qv.z * kv0.z) * rv.z + ftanh(qv.w * kv0.w) * rv.w;
        float sa1 = ftanh(qv.x * kv1.x) * rv.x + ftanh(qv.y * kv1.y) * rv.y
                  + ftanh(qv.z * kv1.z) * rv.z + ftanh(qv.w * kv1.w) * rv.w;
        float sb0 = ftanh(hs.x * hn0.x) * rh.x + ftanh(hs.y * hn0.y) * rh.y;
        float sb1 = ftanh(hs.x * hn1.x) * rh.x + ftanh(hs.y * hn1.y) * rh.y;

        sa0 += __shfl_xor_sync(0xffffffffu, sa0, 1);
        sa1 += __shfl_xor_sync(0xffffffffu, sa1, 1);
        sb0 += __shfl_xor_sync(0xffffffffu, sb0, 1);
        sb1 += __shfl_xor_sync(0xffffffffu, sb1, 1);
        sa0 += __shfl_xor_sync(0xffffffffu, sa0, 2);
        sa1 += __shfl_xor_sync(0xffffffffu, sa1, 2);
        sb0 += __shfl_xor_sync(0xffffffffu, sb0, 2);
        sb1 += __shfl_xor_sync(0xffffffffu, sb1, 2);

        float w0 = __expf(sa0 * sb0 * C);
        float w1 = __expf(sa1 * sb1 * C);
        den += w0 + w1;
        a0 += w0 * kv0.x + w1 * kv1.x;
        a1 += w0 * kv0.y + w1 * kv1.y;
        a2 += w0 * kv0.z + w1 * kv1.z;
        a3 += w0 * kv0.w + w1 * kv1.w;
    }
    if (p < e_end) {
        int o0 = g_csr[p];
        float4 kv0 = *(const float4*)(kbase + o0);
        float2 hn0 = *(const float2*)(hbase + (o0 >> 1));

        float sa0 = ftanh(qv.x * kv0.x) * rv.x + ftanh(qv.y * kv0.y) * rv.y
                  + ftanh(qv.z * kv0.z) * rv.z + ftanh(qv.w * kv0.w) * rv.w;
        float sb0 = ftanh(hs.x * hn0.x) * rh.x + ftanh(hs.y * hn0.y) * rh.y;
        sa0 += __shfl_xor_sync(0xffffffffu, sa0, 1);
        sb0 += __shfl_xor_sync(0xffffffffu, sb0, 1);
        sa0 += __shfl_xor_sync(0xffffffffu, sa0, 2);
        sb0 += __shfl_xor_sync(0xffffffffu, sb0, 2);

        float w0 = __expf(sa0 * sb0 * C);
        den += w0;
        a0 += w0 * kv0.x; a1 += w0 * kv0.y; a2 += w0 * kv0.z; a3 += w0 * kv0.w;
    }

    float inv = __fdividef(1.f, den + 1e-16f);
    float g0 = gelu_exact(a0 * inv), g1 = gelu_exact(a1 * inv);
    float g2 = gelu_exact(a2 * inv), g3 = gelu_exact(a3 * inv);

    float s = g0 + g1 + g2 + g3;
#pragma unroll
    for (int o = 16; o; o >>= 1) s += __shfl_xor_sync(0xffffffffu, s, o);
    float mean = s * (1.0f / 128.0f);

    float d0 = g0 - mean, d1 = g1 - mean, d2 = g2 - mean, d3 = g3 - mean;
    float v = d0 * d0 + d1 * d1 + d2 * d2 + d3 * d3;
#pragma unroll
    for (int o = 16; o; o >>= 1) v += __shfl_xor_sync(0xffffffffu, v, o);
    float rs = rsqrtf(v * (1.0f / 128.0f) + 1e-5f);

    int d = lane * 4;
    float4 gm = *(const float4*)(gamma + d);
    float4 bt = *(const float4*)(beta + d);
    float4 ov;
    ov.x = d0 * rs * gm.x + bt.x;
    ov.y = d1 * rs * gm.y + bt.y;
    ov.z = d2 * rs * gm.z + bt.z;
    ov.w = d3 * rs * gm.w + bt.w;
    *(float4*)(out + n * DDIM + d) = ov;
}

// ---------------- launch ----------------
extern "C" void kernel_launch(void* const* d_in, const int* in_sizes, int n_in,
                              void* d_out, int out_size) {
    const float* meta_xs   = (const float*)d_in[0];
    const int*   node_type = (const int*)d_in[1];
    const int*   edge_idx  = (const int*)d_in[2];
    const float* h_mat     = (const float*)d_in[3];
    const float* sub_W     = (const float*)d_in[4];
    const float* sub_b     = (const float*)d_in[5];
    const float* neigh_W   = (const float*)d_in[6];
    const float* neigh_b   = (const float*)d_in[7];
    const float* hsub_W    = (const float*)d_in[8];
    const float* hsub_b    = (const float*)d_in[9];
    const float* hneigh_W  = (const float*)d_in[10];
    const float* hneigh_b  = (const float*)d_in[11];
    const float* rel_att   = (const float*)d_in[12];
    const float* rel_h_att = (const float*)d_in[13];
    const float* ln_gamma  = (const float*)d_in[14];
    const float* ln_beta   = (const float*)d_in[15];
    float* out = (float*)d_out;

    void* p_z;
    cudaGetSymbolAddress(&p_z, g_zeroed);
    cudaMemsetAsync(p_z, 0, (2 * NN + TT) * sizeof(int));

    k_preA<<<(EE + 255) / 256, 256>>>(edge_idx, node_type);
    k_preB<<<HPROJ_BLOCKS + 1, 1024>>>(h_mat, hsub_W, hsub_b, hneigh_W, hneigh_b);
    k_mid<<<CSR_BLOCKS + PROJ_BLOCKS, 128>>>(meta_xs, sub_W, sub_b,
                                             neigh_W, neigh_b, edge_idx);
    k_edge<<<(NN * 32 + 255) / 256, 256>>>(node_type, rel_att, rel_h_att,
                                           ln_gamma, ln_beta, out);
}